// round 8
// baseline (speedup 1.0000x reference)
#include <cuda_runtime.h>
#include <cstdint>

#define NN 100000
#define EE 1600000
#define INC 128
#define H1C 64      // HEADS*HID
#define HEADS 8
#define OUTC 40

// ---------------- scratch (device globals) -----------------------------------
__device__ float g_h1[NN * H1C];       // layer1 features fp32
__device__ float g_as1[NN * HEADS];
__device__ float g_ad1[NN * HEADS];
__device__ float g_den1[NN * HEADS];   // softmax denom (init e0 by gemm1, red by scatter)
__device__ float g_z[NN * H1C];        // elu(layer1 out)
__device__ float g_h2[NN * OUTC];
__device__ float g_as2[NN];
__device__ float g_ad2[NN];
__device__ float g_den2[NN];           // init e0 by gemm2, red by ew2
// CSR build + edge weights
__device__ int   g_cnt[NN];            // zero-init; re-zeroed by k_gemm1 each run
__device__ int   g_off[NN];
__device__ int   g_cur[NN];            // after scatter: g_cur[i] = off[i] + deg[i]
__device__ int   g_total;              // zero-init; re-zeroed by k_gemm1 each run
__device__ int   g_srcs[EE];
__device__ int   g_dsts[EE];
__device__ float g_wgts[EE];
__device__ float g_eh1[(size_t)EE * 8];  // layer1 per-edge per-head e*wgt
__device__ float g_e2[EE];               // layer2 per-edge e*wgt

__device__ __forceinline__ float leaky(float t) {
    return t > 0.f ? t : 0.2f * t;
}

__device__ __forceinline__ void red4(float* addr, float a, float b, float c, float d) {
    asm volatile("red.global.add.v4.f32 [%0], {%1, %2, %3, %4};"
                 :: "l"(addr), "f"(a), "f"(b), "f"(c), "f"(d) : "memory");
}

__device__ __forceinline__ uint32_t f2tf32(float f) {
    uint32_t u;
    asm("cvt.rna.tf32.f32 %0, %1;" : "=r"(u) : "f"(f));
    return u;
}

__device__ __forceinline__ void mma_tf32(
    float& c0, float& c1, float& c2, float& c3,
    uint32_t a0, uint32_t a1, uint32_t a2, uint32_t a3,
    uint32_t b0, uint32_t b1)
{
    asm volatile(
        "mma.sync.aligned.m16n8k8.row.col.f32.tf32.tf32.f32 "
        "{%0,%1,%2,%3}, {%4,%5,%6,%7}, {%8,%9}, {%0,%1,%2,%3};"
        : "+f"(c0), "+f"(c1), "+f"(c2), "+f"(c3)
        : "r"(a0), "r"(a1), "r"(a2), "r"(a3), "r"(b0), "r"(b1));
}

// ================= K_gemm1: tf32 MMA x@W1 + attention + den1 init + re-zero ==
// block 256 = 8 warps; tile 128 nodes x 64 cols; warp = 16 nodes x 64 cols
__global__ __launch_bounds__(256) void k_gemm1(
    const float* __restrict__ x, const float* __restrict__ W1,
    const float* __restrict__ att_s, const float* __restrict__ att_d)
{
    __shared__ uint32_t ws[128 * 72];   // W1 tf32, pitch 72
    __shared__ uint32_t xs[128 * 20];   // x chunk tf32, pitch 20
    int tid = threadIdx.x;
    int lane = tid & 31;
    int w = tid >> 5;
    int gid = lane >> 2;
    int q = lane & 3;
    int node0 = blockIdx.x * 128;

    // re-zero CSR state for the CSR build that follows (and next replay)
    if (tid < 128) {
        int nz = node0 + tid;
        if (nz < NN) g_cnt[nz] = 0;
    }
    if (blockIdx.x == 0 && tid == 255) g_total = 0;

    {
        const float4* W4 = (const float4*)W1;
#pragma unroll
        for (int i = 0; i < 8; i++) {
            int idx = tid + i * 256;
            int k = idx >> 4, c4 = idx & 15;
            float4 v = __ldg(&W4[idx]);
            uint32_t* p = &ws[k * 72 + c4 * 4];
            p[0] = f2tf32(v.x); p[1] = f2tf32(v.y);
            p[2] = f2tf32(v.z); p[3] = f2tf32(v.w);
        }
    }

    float acc[8][4];
#pragma unroll
    for (int t = 0; t < 8; t++)
#pragma unroll
        for (int j = 0; j < 4; j++) acc[t][j] = 0.f;

    for (int kc = 0; kc < 8; kc++) {
        __syncthreads();
#pragma unroll
        for (int i = 0; i < 2; i++) {
            int idx = tid + i * 256;
            int r = idx >> 2, c4 = idx & 3;
            int n = node0 + r;
            float4 v = make_float4(0.f, 0.f, 0.f, 0.f);
            if (n < NN) v = *(const float4*)(x + (size_t)n * INC + kc * 16 + c4 * 4);
            uint32_t* p = &xs[r * 20 + c4 * 4];
            p[0] = f2tf32(v.x); p[1] = f2tf32(v.y);
            p[2] = f2tf32(v.z); p[3] = f2tf32(v.w);
        }
        __syncthreads();

#pragma unroll
        for (int ks = 0; ks < 2; ks++) {
            int kl = ks * 8;
            int kg = kc * 16 + kl;
            int rbase = (w * 16 + gid) * 20;
            uint32_t a0 = xs[rbase + kl + q];
            uint32_t a1 = xs[rbase + 8 * 20 + kl + q];
            uint32_t a2 = xs[rbase + kl + q + 4];
            uint32_t a3 = xs[rbase + 8 * 20 + kl + q + 4];
#pragma unroll
            for (int t = 0; t < 8; t++) {
                uint32_t b0 = ws[(kg + q) * 72 + t * 8 + gid];
                uint32_t b1 = ws[(kg + q + 4) * 72 + t * 8 + gid];
                mma_tf32(acc[t][0], acc[t][1], acc[t][2], acc[t][3],
                         a0, a1, a2, a3, b0, b1);
            }
        }
    }

    int nlo = node0 + w * 16 + gid;
    int nhi = nlo + 8;
#pragma unroll
    for (int t = 0; t < 8; t++) {
        float av0 = __ldg(&att_s[t * 8 + 2 * q]);
        float av1 = __ldg(&att_s[t * 8 + 2 * q + 1]);
        float dv0 = __ldg(&att_d[t * 8 + 2 * q]);
        float dv1 = __ldg(&att_d[t * 8 + 2 * q + 1]);
        float ps_lo = acc[t][0] * av0 + acc[t][1] * av1;
        float ps_hi = acc[t][2] * av0 + acc[t][3] * av1;
        float pd_lo = acc[t][0] * dv0 + acc[t][1] * dv1;
        float pd_hi = acc[t][2] * dv0 + acc[t][3] * dv1;
        ps_lo += __shfl_xor_sync(~0u, ps_lo, 1);
        ps_lo += __shfl_xor_sync(~0u, ps_lo, 2);
        ps_hi += __shfl_xor_sync(~0u, ps_hi, 1);
        ps_hi += __shfl_xor_sync(~0u, ps_hi, 2);
        pd_lo += __shfl_xor_sync(~0u, pd_lo, 1);
        pd_lo += __shfl_xor_sync(~0u, pd_lo, 2);
        pd_hi += __shfl_xor_sync(~0u, pd_hi, 1);
        pd_hi += __shfl_xor_sync(~0u, pd_hi, 2);

        if (nlo < NN) {
            *(float2*)(g_h1 + (size_t)nlo * H1C + t * 8 + 2 * q) =
                make_float2(acc[t][0], acc[t][1]);
            if (q == (t & 3)) {
                g_as1[nlo * HEADS + t] = ps_lo;
                g_ad1[nlo * HEADS + t] = pd_lo;
                g_den1[nlo * HEADS + t] = __expf(leaky(ps_lo + pd_lo)); // self-loop
            }
        }
        if (nhi < NN) {
            *(float2*)(g_h1 + (size_t)nhi * H1C + t * 8 + 2 * q) =
                make_float2(acc[t][2], acc[t][3]);
            if (q == (t & 3)) {
                g_as1[nhi * HEADS + t] = ps_hi;
                g_ad1[nhi * HEADS + t] = pd_hi;
                g_den1[nhi * HEADS + t] = __expf(leaky(ps_hi + pd_hi)); // self-loop
            }
        }
    }
}

// ================= CSR build ==================================================
__global__ __launch_bounds__(256) void k_hist(const int* __restrict__ ei, int e)
{
    int i = blockIdx.x * 256 + threadIdx.x;
    if (i < e) atomicAdd(&g_cnt[__ldg(&ei[e + i])], 1);
}

__global__ __launch_bounds__(256) void k_off(int n)
{
    __shared__ int swarp[8];
    __shared__ int sbase;
    int tid = threadIdx.x;
    int lane = tid & 31;
    int wid = tid >> 5;
    int i = blockIdx.x * 256 + tid;
    int c = (i < n) ? g_cnt[i] : 0;

    int inc = c;
#pragma unroll
    for (int o = 1; o < 32; o <<= 1) {
        int u = __shfl_up_sync(~0u, inc, o);
        if (lane >= o) inc += u;
    }
    if (lane == 31) swarp[wid] = inc;
    __syncthreads();
    if (tid < 8) {
        int v = swarp[tid];
#pragma unroll
        for (int o = 1; o < 8; o <<= 1) {
            int u = __shfl_up_sync(0xffu, v, o);
            if (tid >= o) v += u;
        }
        swarp[tid] = v;
    }
    __syncthreads();
    int warpbase = wid ? swarp[wid - 1] : 0;
    if (tid == 0) sbase = atomicAdd(&g_total, swarp[7]);
    __syncthreads();
    int off = sbase + warpbase + inc - c;
    if (i < n) {
        g_off[i] = off;
        g_cur[i] = off;
    }
}

// scatter + layer1 edge softmax weights (8 heads) + den1 accumulation
__global__ __launch_bounds__(256) void k_scatter(
    const int* __restrict__ ei, const float* __restrict__ ew, int e)
{
    int i = blockIdx.x * 256 + threadIdx.x;
    if (i >= e) return;
    int s = __ldg(&ei[i]);
    int d = __ldg(&ei[e + i]);
    float w = __ldg(&ew[i]);
    int p = atomicAdd(&g_cur[d], 1);
    g_srcs[p] = s;
    g_dsts[p] = d;
    g_wgts[p] = w;

    float4 a0 = *(const float4*)(g_as1 + s * HEADS);
    float4 a1 = *(const float4*)(g_as1 + s * HEADS + 4);
    float4 b0 = *(const float4*)(g_ad1 + d * HEADS);
    float4 b1 = *(const float4*)(g_ad1 + d * HEADS + 4);
    float e0 = __expf(leaky(a0.x + b0.x));
    float e1 = __expf(leaky(a0.y + b0.y));
    float e2 = __expf(leaky(a0.z + b0.z));
    float e3 = __expf(leaky(a0.w + b0.w));
    float e4 = __expf(leaky(a1.x + b1.x));
    float e5 = __expf(leaky(a1.y + b1.y));
    float e6 = __expf(leaky(a1.z + b1.z));
    float e7 = __expf(leaky(a1.w + b1.w));
    float* ep = g_eh1 + (size_t)p * 8;
    *(float4*)ep       = make_float4(e0 * w, e1 * w, e2 * w, e3 * w);
    *(float4*)(ep + 4) = make_float4(e4 * w, e5 * w, e6 * w, e7 * w);
    red4(g_den1 + d * HEADS,     e0, e1, e2, e3);
    red4(g_den1 + d * HEADS + 4, e4, e5, e6, e7);
}

// ================= K_agg1: warp-per-node gather (layer 1) ====================
__global__ __launch_bounds__(256) void k_agg1(const float* __restrict__ b1, int n)
{
    int d = blockIdx.x * 8 + (threadIdx.x >> 5);
    if (d >= n) return;
    int lane = threadIdx.x & 31;
    int hc = lane >> 2;   // head of channels 2*lane, 2*lane+1

    float den = __ldg(&g_den1[d * HEADS + hc]);
    float e0 = __expf(leaky(__ldg(&g_as1[d * HEADS + hc]) + __ldg(&g_ad1[d * HEADS + hc])));
    float2 hv = *(const float2*)(g_h1 + (size_t)d * H1C + lane * 2);
    float2 acc = make_float2(e0 * hv.x, e0 * hv.y);

    int beg = g_off[d], end = g_cur[d];
    for (int base = beg; base < end; base += 32) {
        int idx = base + lane;
        int src = 0;
        if (idx < end) src = __ldg(&g_srcs[idx]);
        int m = min(32, end - base);
        int m4 = (m + 3) & ~3;
        for (int j = 0; j < m4; j += 4) {
#pragma unroll
            for (int jj = 0; jj < 4; jj++) {
                int jc = j + jj;
                int s = __shfl_sync(0xffffffffu, src, jc);
                float w = 0.f;
                if (jc < m) w = __ldg(&g_eh1[(size_t)(base + jc) * 8 + hc]);
                float2 sv = *(const float2*)(g_h1 + (size_t)s * H1C + lane * 2);
                acc.x += w * sv.x;
                acc.y += w * sv.y;
            }
        }
    }
    float inv = 1.f / (den + 1e-16f);
    float2 bb = *(const float2*)(b1 + lane * 2);
    float zx = acc.x * inv + bb.x;
    float zy = acc.y * inv + bb.y;
    zx = zx > 0.f ? zx : __expf(zx) - 1.f;
    zy = zy > 0.f ? zy : __expf(zy) - 1.f;
    *(float2*)(g_z + (size_t)d * H1C + lane * 2) = make_float2(zx, zy);
}

// ================= K_gemm2: z@W2 + attention + den2 init =====================
__global__ __launch_bounds__(256) void k_gemm2(
    const float* __restrict__ W2, const float* __restrict__ att_s,
    const float* __restrict__ att_d)
{
    __shared__ float sz[128 * 68];
    __shared__ float sw4[64 * 32];
    __shared__ float sw1[64 * 8];
    int tid = threadIdx.x;
    int node0 = blockIdx.x * 128;

    const float4* z4 = (const float4*)g_z;
#pragma unroll
    for (int i = 0; i < 8; i++) {
        int idx = tid + i * 256;
        int r = idx >> 4, c = idx & 15;
        int n = node0 + r;
        float4 v = make_float4(0.f, 0.f, 0.f, 0.f);
        if (n < NN) v = z4[(size_t)n * 16 + c];
        *(float4*)(sz + r * 68 + c * 4) = v;
    }
#pragma unroll
    for (int i = 0; i < 10; i++) {
        int idx = tid + i * 256;
        int k = idx / OUTC, r = idx - k * OUTC;
        int cgg = r / 5, j = r - cgg * 5;
        float v = W2[idx];
        if (j < 4) sw4[k * 32 + cgg * 4 + j] = v;
        else       sw1[k * 8 + cgg] = v;
    }
    __syncthreads();

    int cg = tid & 7;
    int ng = tid >> 3;
    int c0 = cg * 5;
    const float* zr0 = sz + (ng * 4 + 0) * 68;
    const float* zr1 = sz + (ng * 4 + 1) * 68;
    const float* zr2 = sz + (ng * 4 + 2) * 68;
    const float* zr3 = sz + (ng * 4 + 3) * 68;

    float acc[4][5];
#pragma unroll
    for (int i = 0; i < 4; i++)
#pragma unroll
        for (int c = 0; c < 5; c++) acc[i][c] = 0.f;

#pragma unroll 4
    for (int k = 0; k < H1C; k++) {
        float4 w = *(const float4*)(sw4 + k * 32 + cg * 4);
        float w5 = sw1[k * 8 + cg];
        float z0 = zr0[k], z1 = zr1[k], z2 = zr2[k], z3 = zr3[k];
        acc[0][0] += z0 * w.x; acc[0][1] += z0 * w.y; acc[0][2] += z0 * w.z; acc[0][3] += z0 * w.w; acc[0][4] += z0 * w5;
        acc[1][0] += z1 * w.x; acc[1][1] += z1 * w.y; acc[1][2] += z1 * w.z; acc[1][3] += z1 * w.w; acc[1][4] += z1 * w5;
        acc[2][0] += z2 * w.x; acc[2][1] += z2 * w.y; acc[2][2] += z2 * w.z; acc[2][3] += z2 * w.w; acc[2][4] += z2 * w5;
        acc[3][0] += z3 * w.x; acc[3][1] += z3 * w.y; acc[3][2] += z3 * w.z; acc[3][3] += z3 * w.w; acc[3][4] += z3 * w5;
    }

    float ats[5], atd[5];
#pragma unroll
    for (int c = 0; c < 5; c++) { ats[c] = __ldg(&att_s[c0 + c]); atd[c] = __ldg(&att_d[c0 + c]); }

#pragma unroll
    for (int i = 0; i < 4; i++) {
        float s_ = 0.f, d_ = 0.f;
#pragma unroll
        for (int c = 0; c < 5; c++) { s_ += acc[i][c] * ats[c]; d_ += acc[i][c] * atd[c]; }
        s_ += __shfl_xor_sync(0xffffffffu, s_, 1);
        d_ += __shfl_xor_sync(0xffffffffu, d_, 1);
        s_ += __shfl_xor_sync(0xffffffffu, s_, 2);
        d_ += __shfl_xor_sync(0xffffffffu, d_, 2);
        s_ += __shfl_xor_sync(0xffffffffu, s_, 4);
        d_ += __shfl_xor_sync(0xffffffffu, d_, 4);
        int nd = node0 + ng * 4 + i;
        if (nd < NN) {
            if (cg == 0) {
                g_as2[nd] = s_;
                g_ad2[nd] = d_;
                g_den2[nd] = __expf(leaky(s_ + d_));   // self-loop
            }
            float* hp = g_h2 + (size_t)nd * OUTC + c0;
#pragma unroll
            for (int c = 0; c < 5; c++) hp[c] = acc[i][c];
        }
    }
}

// ================= K_ew2: layer-2 per-edge weights + den2 ====================
__global__ __launch_bounds__(256) void k_ew2(int e)
{
    int i = blockIdx.x * 256 + threadIdx.x;
    if (i >= e) return;
    int s = __ldg(&g_srcs[i]);
    int d = __ldg(&g_dsts[i]);
    float w = __ldg(&g_wgts[i]);
    float ev = __expf(leaky(__ldg(&g_as2[s]) + __ldg(&g_ad2[d])));
    g_e2[i] = ev * w;
    atomicAdd(&g_den2[d], ev);
}

// ================= K_agg2: warp-per-node gather (layer 2) + output ===========
__global__ __launch_bounds__(256) void k_agg2(
    float* __restrict__ out, const float* __restrict__ b2, int n)
{
    int d = blockIdx.x * 8 + (threadIdx.x >> 5);
    if (d >= n) return;
    int lane = threadIdx.x & 31;

    float den = __ldg(&g_den2[d]);
    float e0 = __expf(leaky(__ldg(&g_as2[d]) + __ldg(&g_ad2[d])));
    float2 acc = make_float2(0.f, 0.f);
    if (lane < 20) {
        float2 hv = *(const float2*)(g_h2 + (size_t)d * OUTC + lane * 2);
        acc.x = e0 * hv.x;
        acc.y = e0 * hv.y;
    }

    int beg = g_off[d], end = g_cur[d];
    for (int base = beg; base < end; base += 32) {
        int idx = base + lane;
        int src = 0;
        if (idx < end) src = __ldg(&g_srcs[idx]);
        int m = min(32, end - base);
        int m4 = (m + 3) & ~3;
        for (int j = 0; j < m4; j += 4) {
#pragma unroll
            for (int jj = 0; jj < 4; jj++) {
                int jc = j + jj;
                int s = __shfl_sync(0xffffffffu, src, jc);
                float w = 0.f;
                if (jc < m) w = __ldg(&g_e2[base + jc]);
                if (lane < 20) {
                    float2 sv = *(const float2*)(g_h2 + (size_t)s * OUTC + lane * 2);
                    acc.x += w * sv.x;
                    acc.y += w * sv.y;
                }
            }
        }
    }
    float inv = 1.f / (den + 1e-16f);
    if (lane < 20) {
        float2 bb = *(const float2*)(b2 + lane * 2);
        float2 r = make_float2(acc.x * inv + bb.x, acc.y * inv + bb.y);
        *(float2*)(out + (size_t)d * OUTC + lane * 2) = r;
    }
}

// -----------------------------------------------------------------------------
extern "C" void kernel_launch(void* const* d_in, const int* in_sizes, int n_in,
                              void* d_out, int out_size)
{
    const float* x   = (const float*)d_in[0];
    const int*   ei  = (const int*)d_in[1];
    const float* ew  = (const float*)d_in[2];
    const float* W1  = (const float*)d_in[3];
    const float* as1 = (const float*)d_in[4];
    const float* ad1 = (const float*)d_in[5];
    const float* b1  = (const float*)d_in[6];
    const float* W2  = (const float*)d_in[7];
    const float* as2 = (const float*)d_in[8];
    const float* ad2 = (const float*)d_in[9];
    const float* b2  = (const float*)d_in[10];

    int n = in_sizes[0] / INC;       // 100000
    int e = in_sizes[2];             // 1600000

    // gemm1 first: produces as1/ad1/den1(self) AND re-zeros g_cnt/g_total
    k_gemm1<<<(n + 127) / 128, 256>>>(x, W1, as1, ad1);
    // CSR build + layer1 edge weights
    k_hist<<<(e + 255) / 256, 256>>>(ei, e);
    k_off<<<(n + 255) / 256, 256>>>(n);
    k_scatter<<<(e + 255) / 256, 256>>>(ei, ew, e);
    // layer 1 aggregation
    k_agg1<<<(n + 7) / 8, 256>>>(b1, n);
    // layer 2
    k_gemm2<<<(n + 127) / 128, 256>>>(W2, as2, ad2);
    k_ew2<<<(e + 255) / 256, 256>>>(e);
    k_agg2<<<(n + 7) / 8, 256>>>((float*)d_out, b2, n);
}

// round 9
// speedup vs baseline: 1.0781x; 1.0781x over previous
#include <cuda_runtime.h>
#include <cstdint>

#define NN 100000
#define EE 1600000
#define INC 128
#define H1C 64      // HEADS*HID
#define HEADS 8
#define OUTC 40

// ---------------- scratch (device globals) -----------------------------------
__device__ float g_h1[NN * H1C];       // layer1 features fp32
__device__ float g_as1[NN * HEADS];
__device__ float g_ad1[NN * HEADS];
__device__ float g_z[NN * H1C];        // elu(layer1 out)
__device__ float g_h2[NN * OUTC];
__device__ float g_as2[NN];
__device__ float g_ad2[NN];
// CSR build + edge weights
__device__ int   g_cnt[NN];            // zero-init; re-zeroed by k_gemm1 each run
__device__ int   g_off[NN];
__device__ int   g_cur[NN];            // after scatter: g_cur[i] = off[i] + deg[i]
__device__ int   g_total;              // zero-init; re-zeroed by k_gemm1 each run
__device__ int   g_srcs[EE];
__device__ int   g_dsts[EE];
__device__ float g_wgts[EE];
__device__ float g_eh1[(size_t)EE * 8];  // layer1 per-slot per-head raw e
__device__ float g_e2[EE];               // layer2 per-slot raw e

__device__ __forceinline__ float leaky(float t) {
    return t > 0.f ? t : 0.2f * t;
}

__device__ __forceinline__ uint32_t f2tf32(float f) {
    uint32_t u;
    asm("cvt.rna.tf32.f32 %0, %1;" : "=r"(u) : "f"(f));
    return u;
}

__device__ __forceinline__ void mma_tf32(
    float& c0, float& c1, float& c2, float& c3,
    uint32_t a0, uint32_t a1, uint32_t a2, uint32_t a3,
    uint32_t b0, uint32_t b1)
{
    asm volatile(
        "mma.sync.aligned.m16n8k8.row.col.f32.tf32.tf32.f32 "
        "{%0,%1,%2,%3}, {%4,%5,%6,%7}, {%8,%9}, {%0,%1,%2,%3};"
        : "+f"(c0), "+f"(c1), "+f"(c2), "+f"(c3)
        : "r"(a0), "r"(a1), "r"(a2), "r"(a3), "r"(b0), "r"(b1));
}

// ================= K_gemm1: tf32 MMA x@W1 + attention + re-zero ==============
// block 256 = 8 warps; tile 128 nodes x 64 cols; warp = 16 nodes x 64 cols
__global__ __launch_bounds__(256) void k_gemm1(
    const float* __restrict__ x, const float* __restrict__ W1,
    const float* __restrict__ att_s, const float* __restrict__ att_d)
{
    __shared__ uint32_t ws[128 * 72];   // W1 tf32, pitch 72
    __shared__ uint32_t xs[128 * 20];   // x chunk tf32, pitch 20
    int tid = threadIdx.x;
    int lane = tid & 31;
    int w = tid >> 5;
    int gid = lane >> 2;
    int q = lane & 3;
    int node0 = blockIdx.x * 128;

    // re-zero CSR state for the CSR build that follows (and next replay)
    if (tid < 128) {
        int nz = node0 + tid;
        if (nz < NN) g_cnt[nz] = 0;
    }
    if (blockIdx.x == 0 && tid == 255) g_total = 0;

    {
        const float4* W4 = (const float4*)W1;
#pragma unroll
        for (int i = 0; i < 8; i++) {
            int idx = tid + i * 256;
            int k = idx >> 4, c4 = idx & 15;
            float4 v = __ldg(&W4[idx]);
            uint32_t* p = &ws[k * 72 + c4 * 4];
            p[0] = f2tf32(v.x); p[1] = f2tf32(v.y);
            p[2] = f2tf32(v.z); p[3] = f2tf32(v.w);
        }
    }

    float acc[8][4];
#pragma unroll
    for (int t = 0; t < 8; t++)
#pragma unroll
        for (int j = 0; j < 4; j++) acc[t][j] = 0.f;

    for (int kc = 0; kc < 8; kc++) {
        __syncthreads();
#pragma unroll
        for (int i = 0; i < 2; i++) {
            int idx = tid + i * 256;
            int r = idx >> 2, c4 = idx & 3;
            int n = node0 + r;
            float4 v = make_float4(0.f, 0.f, 0.f, 0.f);
            if (n < NN) v = *(const float4*)(x + (size_t)n * INC + kc * 16 + c4 * 4);
            uint32_t* p = &xs[r * 20 + c4 * 4];
            p[0] = f2tf32(v.x); p[1] = f2tf32(v.y);
            p[2] = f2tf32(v.z); p[3] = f2tf32(v.w);
        }
        __syncthreads();

#pragma unroll
        for (int ks = 0; ks < 2; ks++) {
            int kl = ks * 8;
            int kg = kc * 16 + kl;
            int rbase = (w * 16 + gid) * 20;
            uint32_t a0 = xs[rbase + kl + q];
            uint32_t a1 = xs[rbase + 8 * 20 + kl + q];
            uint32_t a2 = xs[rbase + kl + q + 4];
            uint32_t a3 = xs[rbase + 8 * 20 + kl + q + 4];
#pragma unroll
            for (int t = 0; t < 8; t++) {
                uint32_t b0 = ws[(kg + q) * 72 + t * 8 + gid];
                uint32_t b1 = ws[(kg + q + 4) * 72 + t * 8 + gid];
                mma_tf32(acc[t][0], acc[t][1], acc[t][2], acc[t][3],
                         a0, a1, a2, a3, b0, b1);
            }
        }
    }

    int nlo = node0 + w * 16 + gid;
    int nhi = nlo + 8;
#pragma unroll
    for (int t = 0; t < 8; t++) {
        float av0 = __ldg(&att_s[t * 8 + 2 * q]);
        float av1 = __ldg(&att_s[t * 8 + 2 * q + 1]);
        float dv0 = __ldg(&att_d[t * 8 + 2 * q]);
        float dv1 = __ldg(&att_d[t * 8 + 2 * q + 1]);
        float ps_lo = acc[t][0] * av0 + acc[t][1] * av1;
        float ps_hi = acc[t][2] * av0 + acc[t][3] * av1;
        float pd_lo = acc[t][0] * dv0 + acc[t][1] * dv1;
        float pd_hi = acc[t][2] * dv0 + acc[t][3] * dv1;
        ps_lo += __shfl_xor_sync(~0u, ps_lo, 1);
        ps_lo += __shfl_xor_sync(~0u, ps_lo, 2);
        ps_hi += __shfl_xor_sync(~0u, ps_hi, 1);
        ps_hi += __shfl_xor_sync(~0u, ps_hi, 2);
        pd_lo += __shfl_xor_sync(~0u, pd_lo, 1);
        pd_lo += __shfl_xor_sync(~0u, pd_lo, 2);
        pd_hi += __shfl_xor_sync(~0u, pd_hi, 1);
        pd_hi += __shfl_xor_sync(~0u, pd_hi, 2);

        if (nlo < NN) {
            *(float2*)(g_h1 + (size_t)nlo * H1C + t * 8 + 2 * q) =
                make_float2(acc[t][0], acc[t][1]);
            if (q == (t & 3)) {
                g_as1[nlo * HEADS + t] = ps_lo;
                g_ad1[nlo * HEADS + t] = pd_lo;
            }
        }
        if (nhi < NN) {
            *(float2*)(g_h1 + (size_t)nhi * H1C + t * 8 + 2 * q) =
                make_float2(acc[t][2], acc[t][3]);
            if (q == (t & 3)) {
                g_as1[nhi * HEADS + t] = ps_hi;
                g_ad1[nhi * HEADS + t] = pd_hi;
            }
        }
    }
}

// ================= CSR build ==================================================
__global__ __launch_bounds__(256) void k_hist(const int* __restrict__ ei, int e)
{
    int i = blockIdx.x * 256 + threadIdx.x;
    if (i < e) atomicAdd(&g_cnt[__ldg(&ei[e + i])], 1);
}

__global__ __launch_bounds__(256) void k_off(int n)
{
    __shared__ int swarp[8];
    __shared__ int sbase;
    int tid = threadIdx.x;
    int lane = tid & 31;
    int wid = tid >> 5;
    int i = blockIdx.x * 256 + tid;
    int c = (i < n) ? g_cnt[i] : 0;

    int inc = c;
#pragma unroll
    for (int o = 1; o < 32; o <<= 1) {
        int u = __shfl_up_sync(~0u, inc, o);
        if (lane >= o) inc += u;
    }
    if (lane == 31) swarp[wid] = inc;
    __syncthreads();
    if (tid < 8) {
        int v = swarp[tid];
#pragma unroll
        for (int o = 1; o < 8; o <<= 1) {
            int u = __shfl_up_sync(0xffu, v, o);
            if (tid >= o) v += u;
        }
        swarp[tid] = v;
    }
    __syncthreads();
    int warpbase = wid ? swarp[wid - 1] : 0;
    if (tid == 0) sbase = atomicAdd(&g_total, swarp[7]);
    __syncthreads();
    int off = sbase + warpbase + inc - c;
    if (i < n) {
        g_off[i] = off;
        g_cur[i] = off;
    }
}

__global__ __launch_bounds__(256) void k_scatter(
    const int* __restrict__ ei, const float* __restrict__ ew, int e)
{
    int i = blockIdx.x * 256 + threadIdx.x;
    if (i >= e) return;
    int s = __ldg(&ei[i]);
    int d = __ldg(&ei[e + i]);
    int p = atomicAdd(&g_cur[d], 1);
    g_srcs[p] = s;
    g_dsts[p] = d;
    g_wgts[p] = __ldg(&ew[i]);
}

// ================= K_ew1: per-slot raw exps (8 heads), slot order ============
__global__ __launch_bounds__(256) void k_ew1(int e)
{
    int i = blockIdx.x * 256 + threadIdx.x;
    if (i >= e) return;
    int s = __ldg(&g_srcs[i]);
    int d = __ldg(&g_dsts[i]);   // slots grouped by d -> cached reads
    float4 a0 = *(const float4*)(g_as1 + s * HEADS);
    float4 a1 = *(const float4*)(g_as1 + s * HEADS + 4);
    float4 b0 = *(const float4*)(g_ad1 + d * HEADS);
    float4 b1 = *(const float4*)(g_ad1 + d * HEADS + 4);
    float* ep = g_eh1 + (size_t)i * 8;
    *(float4*)ep = make_float4(
        __expf(leaky(a0.x + b0.x)), __expf(leaky(a0.y + b0.y)),
        __expf(leaky(a0.z + b0.z)), __expf(leaky(a0.w + b0.w)));
    *(float4*)(ep + 4) = make_float4(
        __expf(leaky(a1.x + b1.x)), __expf(leaky(a1.y + b1.y)),
        __expf(leaky(a1.z + b1.z)), __expf(leaky(a1.w + b1.w)));
}

// ================= K_agg1: warp-per-node gather (layer 1) ====================
__global__ __launch_bounds__(256) void k_agg1(const float* __restrict__ b1, int n)
{
    int d = blockIdx.x * 8 + (threadIdx.x >> 5);
    if (d >= n) return;
    int lane = threadIdx.x & 31;
    int hc = lane >> 2;   // head of channels 2*lane, 2*lane+1

    // self-loop (ew = 1)
    float e0 = __expf(leaky(__ldg(&g_as1[d * HEADS + hc]) + __ldg(&g_ad1[d * HEADS + hc])));
    float den = e0;
    float2 hv = *(const float2*)(g_h1 + (size_t)d * H1C + lane * 2);
    float2 acc = make_float2(e0 * hv.x, e0 * hv.y);

    int beg = g_off[d], end = g_cur[d];
    for (int base = beg; base < end; base += 32) {
        int idx = base + lane;
        int src = 0; float wgt = 0.f;
        if (idx < end) {
            src = __ldg(&g_srcs[idx]);
            wgt = __ldg(&g_wgts[idx]);
        }
        int m = min(32, end - base);
        int m4 = (m + 3) & ~3;
        for (int j = 0; j < m4; j += 4) {
#pragma unroll
            for (int jj = 0; jj < 4; jj++) {
                int jc = j + jj;
                int s = __shfl_sync(0xffffffffu, src, jc);
                float wj = __shfl_sync(0xffffffffu, wgt, jc);
                float ev = 0.f;
                if (jc < m) ev = __ldg(&g_eh1[(size_t)(base + jc) * 8 + hc]); // streaming
                den += ev;
                float w = ev * wj;
                float2 sv = *(const float2*)(g_h1 + (size_t)s * H1C + lane * 2);
                acc.x += w * sv.x;
                acc.y += w * sv.y;
            }
        }
    }
    float inv = 1.f / (den + 1e-16f);
    float2 bb = *(const float2*)(b1 + lane * 2);
    float zx = acc.x * inv + bb.x;
    float zy = acc.y * inv + bb.y;
    zx = zx > 0.f ? zx : __expf(zx) - 1.f;
    zy = zy > 0.f ? zy : __expf(zy) - 1.f;
    *(float2*)(g_z + (size_t)d * H1C + lane * 2) = make_float2(zx, zy);
}

// ================= K_gemm2: z@W2 + attention ==================================
__global__ __launch_bounds__(256) void k_gemm2(
    const float* __restrict__ W2, const float* __restrict__ att_s,
    const float* __restrict__ att_d)
{
    __shared__ float sz[128 * 68];
    __shared__ float sw4[64 * 32];
    __shared__ float sw1[64 * 8];
    int tid = threadIdx.x;
    int node0 = blockIdx.x * 128;

    const float4* z4 = (const float4*)g_z;
#pragma unroll
    for (int i = 0; i < 8; i++) {
        int idx = tid + i * 256;
        int r = idx >> 4, c = idx & 15;
        int n = node0 + r;
        float4 v = make_float4(0.f, 0.f, 0.f, 0.f);
        if (n < NN) v = z4[(size_t)n * 16 + c];
        *(float4*)(sz + r * 68 + c * 4) = v;
    }
#pragma unroll
    for (int i = 0; i < 10; i++) {
        int idx = tid + i * 256;
        int k = idx / OUTC, r = idx - k * OUTC;
        int cgg = r / 5, j = r - cgg * 5;
        float v = W2[idx];
        if (j < 4) sw4[k * 32 + cgg * 4 + j] = v;
        else       sw1[k * 8 + cgg] = v;
    }
    __syncthreads();

    int cg = tid & 7;
    int ng = tid >> 3;
    int c0 = cg * 5;
    const float* zr0 = sz + (ng * 4 + 0) * 68;
    const float* zr1 = sz + (ng * 4 + 1) * 68;
    const float* zr2 = sz + (ng * 4 + 2) * 68;
    const float* zr3 = sz + (ng * 4 + 3) * 68;

    float acc[4][5];
#pragma unroll
    for (int i = 0; i < 4; i++)
#pragma unroll
        for (int c = 0; c < 5; c++) acc[i][c] = 0.f;

#pragma unroll 4
    for (int k = 0; k < H1C; k++) {
        float4 w = *(const float4*)(sw4 + k * 32 + cg * 4);
        float w5 = sw1[k * 8 + cg];
        float z0 = zr0[k], z1 = zr1[k], z2 = zr2[k], z3 = zr3[k];
        acc[0][0] += z0 * w.x; acc[0][1] += z0 * w.y; acc[0][2] += z0 * w.z; acc[0][3] += z0 * w.w; acc[0][4] += z0 * w5;
        acc[1][0] += z1 * w.x; acc[1][1] += z1 * w.y; acc[1][2] += z1 * w.z; acc[1][3] += z1 * w.w; acc[1][4] += z1 * w5;
        acc[2][0] += z2 * w.x; acc[2][1] += z2 * w.y; acc[2][2] += z2 * w.z; acc[2][3] += z2 * w.w; acc[2][4] += z2 * w5;
        acc[3][0] += z3 * w.x; acc[3][1] += z3 * w.y; acc[3][2] += z3 * w.z; acc[3][3] += z3 * w.w; acc[3][4] += z3 * w5;
    }

    float ats[5], atd[5];
#pragma unroll
    for (int c = 0; c < 5; c++) { ats[c] = __ldg(&att_s[c0 + c]); atd[c] = __ldg(&att_d[c0 + c]); }

#pragma unroll
    for (int i = 0; i < 4; i++) {
        float s_ = 0.f, d_ = 0.f;
#pragma unroll
        for (int c = 0; c < 5; c++) { s_ += acc[i][c] * ats[c]; d_ += acc[i][c] * atd[c]; }
        s_ += __shfl_xor_sync(0xffffffffu, s_, 1);
        d_ += __shfl_xor_sync(0xffffffffu, d_, 1);
        s_ += __shfl_xor_sync(0xffffffffu, s_, 2);
        d_ += __shfl_xor_sync(0xffffffffu, d_, 2);
        s_ += __shfl_xor_sync(0xffffffffu, s_, 4);
        d_ += __shfl_xor_sync(0xffffffffu, d_, 4);
        int nd = node0 + ng * 4 + i;
        if (nd < NN) {
            if (cg == 0) {
                g_as2[nd] = s_;
                g_ad2[nd] = d_;
            }
            float* hp = g_h2 + (size_t)nd * OUTC + c0;
#pragma unroll
            for (int c = 0; c < 5; c++) hp[c] = acc[i][c];
        }
    }
}

// ================= K_ew2: per-slot raw exp (layer 2) =========================
__global__ __launch_bounds__(256) void k_ew2(int e)
{
    int i = blockIdx.x * 256 + threadIdx.x;
    if (i >= e) return;
    int s = __ldg(&g_srcs[i]);
    int d = __ldg(&g_dsts[i]);
    g_e2[i] = __expf(leaky(__ldg(&g_as2[s]) + __ldg(&g_ad2[d])));
}

// ================= K_agg2: warp-per-node gather (layer 2) + output ===========
__global__ __launch_bounds__(256) void k_agg2(
    float* __restrict__ out, const float* __restrict__ b2, int n)
{
    int d = blockIdx.x * 8 + (threadIdx.x >> 5);
    if (d >= n) return;
    int lane = threadIdx.x & 31;

    float e0 = __expf(leaky(__ldg(&g_as2[d]) + __ldg(&g_ad2[d])));   // self loop
    float den = e0;
    float2 acc = make_float2(0.f, 0.f);
    if (lane < 20) {
        float2 hv = *(const float2*)(g_h2 + (size_t)d * OUTC + lane * 2);
        acc.x = e0 * hv.x;
        acc.y = e0 * hv.y;
    }

    int beg = g_off[d], end = g_cur[d];
    for (int base = beg; base < end; base += 32) {
        int idx = base + lane;
        int src = 0; float wgt = 0.f;
        if (idx < end) {
            src = __ldg(&g_srcs[idx]);
            wgt = __ldg(&g_wgts[idx]);
        }
        int m = min(32, end - base);
        int m4 = (m + 3) & ~3;
        for (int j = 0; j < m4; j += 4) {
#pragma unroll
            for (int jj = 0; jj < 4; jj++) {
                int jc = j + jj;
                int s = __shfl_sync(0xffffffffu, src, jc);
                float wj = __shfl_sync(0xffffffffu, wgt, jc);
                float ev = 0.f;
                if (jc < m) ev = __ldg(&g_e2[base + jc]);   // broadcast load
                den += ev;
                float w = ev * wj;
                if (lane < 20) {
                    float2 sv = *(const float2*)(g_h2 + (size_t)s * OUTC + lane * 2);
                    acc.x += w * sv.x;
                    acc.y += w * sv.y;
                }
            }
        }
    }
    float inv = 1.f / (den + 1e-16f);
    if (lane < 20) {
        float2 bb = *(const float2*)(b2 + lane * 2);
        float2 r = make_float2(acc.x * inv + bb.x, acc.y * inv + bb.y);
        *(float2*)(out + (size_t)d * OUTC + lane * 2) = r;
    }
}

// -----------------------------------------------------------------------------
extern "C" void kernel_launch(void* const* d_in, const int* in_sizes, int n_in,
                              void* d_out, int out_size)
{
    const float* x   = (const float*)d_in[0];
    const int*   ei  = (const int*)d_in[1];
    const float* ew  = (const float*)d_in[2];
    const float* W1  = (const float*)d_in[3];
    const float* as1 = (const float*)d_in[4];
    const float* ad1 = (const float*)d_in[5];
    const float* b1  = (const float*)d_in[6];
    const float* W2  = (const float*)d_in[7];
    const float* as2 = (const float*)d_in[8];
    const float* ad2 = (const float*)d_in[9];
    const float* b2  = (const float*)d_in[10];

    int n = in_sizes[0] / INC;       // 100000
    int e = in_sizes[2];             // 1600000

    // gemm1 first: produces h1/as1/ad1 AND re-zeros g_cnt/g_total
    k_gemm1<<<(n + 127) / 128, 256>>>(x, W1, as1, ad1);
    // CSR build
    k_hist<<<(e + 255) / 256, 256>>>(ei, e);
    k_off<<<(n + 255) / 256, 256>>>(n);
    k_scatter<<<(e + 255) / 256, 256>>>(ei, ew, e);
    // layer 1 edge exps + aggregation
    k_ew1<<<(e + 255) / 256, 256>>>(e);
    k_agg1<<<(n + 7) / 8, 256>>>(b1, n);
    // layer 2
    k_gemm2<<<(n + 127) / 128, 256>>>(W2, as2, ad2);
    k_ew2<<<(e + 255) / 256, 256>>>(e);
    k_agg2<<<(n + 7) / 8, 256>>>((float*)d_out, b2, n);
}

// round 10
// speedup vs baseline: 1.3251x; 1.2291x over previous
#include <cuda_runtime.h>
#include <cstdint>

#define NN 100000
#define EE 1600000
#define INC 128
#define H1C 64      // HEADS*HID
#define HEADS 8
#define OUTC 40

// ---------------- scratch (device globals) -----------------------------------
__device__ float g_h1[NN * H1C];       // layer1 features fp32
__device__ float g_as1[NN * HEADS];
__device__ float g_ad1[NN * HEADS];
__device__ float g_z[NN * H1C];        // elu(layer1 out)
__device__ float g_h2[NN * OUTC];
__device__ float g_as2[NN];
__device__ float g_ad2[NN];
// CSR build
__device__ int   g_cnt[NN];            // zero-init; re-zeroed by k_gemm1 each run
__device__ int   g_off[NN];
__device__ int   g_cur[NN];            // after scatter: g_cur[i] = off[i] + deg[i]
__device__ int   g_total;              // zero-init; re-zeroed by k_gemm1 each run
__device__ int2  g_sw[EE];             // packed {src, wgt bits} per slot

__device__ __forceinline__ float leaky(float t) {
    return t > 0.f ? t : 0.2f * t;
}

__device__ __forceinline__ uint32_t f2tf32(float f) {
    uint32_t u;
    asm("cvt.rna.tf32.f32 %0, %1;" : "=r"(u) : "f"(f));
    return u;
}

__device__ __forceinline__ void mma_tf32(
    float& c0, float& c1, float& c2, float& c3,
    uint32_t a0, uint32_t a1, uint32_t a2, uint32_t a3,
    uint32_t b0, uint32_t b1)
{
    asm volatile(
        "mma.sync.aligned.m16n8k8.row.col.f32.tf32.tf32.f32 "
        "{%0,%1,%2,%3}, {%4,%5,%6,%7}, {%8,%9}, {%0,%1,%2,%3};"
        : "+f"(c0), "+f"(c1), "+f"(c2), "+f"(c3)
        : "r"(a0), "r"(a1), "r"(a2), "r"(a3), "r"(b0), "r"(b1));
}

// ================= K_gemm1: tf32 MMA x@W1 + attention + re-zero ==============
// block 256 = 8 warps; tile 128 nodes x 64 cols; warp = 16 nodes x 64 cols
__global__ __launch_bounds__(256) void k_gemm1(
    const float* __restrict__ x, const float* __restrict__ W1,
    const float* __restrict__ att_s, const float* __restrict__ att_d)
{
    __shared__ uint32_t ws[128 * 72];   // W1 tf32, pitch 72
    __shared__ uint32_t xs[128 * 20];   // x chunk tf32, pitch 20
    int tid = threadIdx.x;
    int lane = tid & 31;
    int w = tid >> 5;
    int gid = lane >> 2;
    int q = lane & 3;
    int node0 = blockIdx.x * 128;

    // re-zero CSR state for the CSR build that follows (and next replay)
    if (tid < 128) {
        int nz = node0 + tid;
        if (nz < NN) g_cnt[nz] = 0;
    }
    if (blockIdx.x == 0 && tid == 255) g_total = 0;

    {
        const float4* W4 = (const float4*)W1;
#pragma unroll
        for (int i = 0; i < 8; i++) {
            int idx = tid + i * 256;
            int k = idx >> 4, c4 = idx & 15;
            float4 v = __ldg(&W4[idx]);
            uint32_t* p = &ws[k * 72 + c4 * 4];
            p[0] = f2tf32(v.x); p[1] = f2tf32(v.y);
            p[2] = f2tf32(v.z); p[3] = f2tf32(v.w);
        }
    }

    float acc[8][4];
#pragma unroll
    for (int t = 0; t < 8; t++)
#pragma unroll
        for (int j = 0; j < 4; j++) acc[t][j] = 0.f;

    for (int kc = 0; kc < 8; kc++) {
        __syncthreads();
#pragma unroll
        for (int i = 0; i < 2; i++) {
            int idx = tid + i * 256;
            int r = idx >> 2, c4 = idx & 3;
            int n = node0 + r;
            float4 v = make_float4(0.f, 0.f, 0.f, 0.f);
            if (n < NN) v = *(const float4*)(x + (size_t)n * INC + kc * 16 + c4 * 4);
            uint32_t* p = &xs[r * 20 + c4 * 4];
            p[0] = f2tf32(v.x); p[1] = f2tf32(v.y);
            p[2] = f2tf32(v.z); p[3] = f2tf32(v.w);
        }
        __syncthreads();

#pragma unroll
        for (int ks = 0; ks < 2; ks++) {
            int kl = ks * 8;
            int kg = kc * 16 + kl;
            int rbase = (w * 16 + gid) * 20;
            uint32_t a0 = xs[rbase + kl + q];
            uint32_t a1 = xs[rbase + 8 * 20 + kl + q];
            uint32_t a2 = xs[rbase + kl + q + 4];
            uint32_t a3 = xs[rbase + 8 * 20 + kl + q + 4];
#pragma unroll
            for (int t = 0; t < 8; t++) {
                uint32_t b0 = ws[(kg + q) * 72 + t * 8 + gid];
                uint32_t b1 = ws[(kg + q + 4) * 72 + t * 8 + gid];
                mma_tf32(acc[t][0], acc[t][1], acc[t][2], acc[t][3],
                         a0, a1, a2, a3, b0, b1);
            }
        }
    }

    int nlo = node0 + w * 16 + gid;
    int nhi = nlo + 8;
#pragma unroll
    for (int t = 0; t < 8; t++) {
        float av0 = __ldg(&att_s[t * 8 + 2 * q]);
        float av1 = __ldg(&att_s[t * 8 + 2 * q + 1]);
        float dv0 = __ldg(&att_d[t * 8 + 2 * q]);
        float dv1 = __ldg(&att_d[t * 8 + 2 * q + 1]);
        float ps_lo = acc[t][0] * av0 + acc[t][1] * av1;
        float ps_hi = acc[t][2] * av0 + acc[t][3] * av1;
        float pd_lo = acc[t][0] * dv0 + acc[t][1] * dv1;
        float pd_hi = acc[t][2] * dv0 + acc[t][3] * dv1;
        ps_lo += __shfl_xor_sync(~0u, ps_lo, 1);
        ps_lo += __shfl_xor_sync(~0u, ps_lo, 2);
        ps_hi += __shfl_xor_sync(~0u, ps_hi, 1);
        ps_hi += __shfl_xor_sync(~0u, ps_hi, 2);
        pd_lo += __shfl_xor_sync(~0u, pd_lo, 1);
        pd_lo += __shfl_xor_sync(~0u, pd_lo, 2);
        pd_hi += __shfl_xor_sync(~0u, pd_hi, 1);
        pd_hi += __shfl_xor_sync(~0u, pd_hi, 2);

        if (nlo < NN) {
            *(float2*)(g_h1 + (size_t)nlo * H1C + t * 8 + 2 * q) =
                make_float2(acc[t][0], acc[t][1]);
            if (q == (t & 3)) {
                g_as1[nlo * HEADS + t] = ps_lo;
                g_ad1[nlo * HEADS + t] = pd_lo;
            }
        }
        if (nhi < NN) {
            *(float2*)(g_h1 + (size_t)nhi * H1C + t * 8 + 2 * q) =
                make_float2(acc[t][2], acc[t][3]);
            if (q == (t & 3)) {
                g_as1[nhi * HEADS + t] = ps_hi;
                g_ad1[nhi * HEADS + t] = pd_hi;
            }
        }
    }
}

// ================= CSR build ==================================================
__global__ __launch_bounds__(256) void k_hist(const int* __restrict__ ei, int e)
{
    int i = blockIdx.x * 256 + threadIdx.x;
    if (i < e) atomicAdd(&g_cnt[__ldg(&ei[e + i])], 1);
}

__global__ __launch_bounds__(256) void k_off(int n)
{
    __shared__ int swarp[8];
    __shared__ int sbase;
    int tid = threadIdx.x;
    int lane = tid & 31;
    int wid = tid >> 5;
    int i = blockIdx.x * 256 + tid;
    int c = (i < n) ? g_cnt[i] : 0;

    int inc = c;
#pragma unroll
    for (int o = 1; o < 32; o <<= 1) {
        int u = __shfl_up_sync(~0u, inc, o);
        if (lane >= o) inc += u;
    }
    if (lane == 31) swarp[wid] = inc;
    __syncthreads();
    if (tid < 8) {
        int v = swarp[tid];
#pragma unroll
        for (int o = 1; o < 8; o <<= 1) {
            int u = __shfl_up_sync(0xffu, v, o);
            if (tid >= o) v += u;
        }
        swarp[tid] = v;
    }
    __syncthreads();
    int warpbase = wid ? swarp[wid - 1] : 0;
    if (tid == 0) sbase = atomicAdd(&g_total, swarp[7]);
    __syncthreads();
    int off = sbase + warpbase + inc - c;
    if (i < n) {
        g_off[i] = off;
        g_cur[i] = off;
    }
}

__global__ __launch_bounds__(256) void k_scatter(
    const int* __restrict__ ei, const float* __restrict__ ew, int e)
{
    int i = blockIdx.x * 256 + threadIdx.x;
    if (i >= e) return;
    int s = __ldg(&ei[i]);
    int d = __ldg(&ei[e + i]);
    float w = __ldg(&ew[i]);
    int p = atomicAdd(&g_cur[d], 1);
    g_sw[p] = make_int2(s, __float_as_int(w));   // single 8B random store
}

// ================= K_agg1: warp-per-node gather (layer 1) ====================
// per-lane exp for its own head hc; den falls out per-lane; unroll 8
__global__ __launch_bounds__(256) void k_agg1(const float* __restrict__ b1, int n)
{
    int d = blockIdx.x * 8 + (threadIdx.x >> 5);
    if (d >= n) return;
    int lane = threadIdx.x & 31;
    int hc = lane >> 2;   // head of channels 2*lane, 2*lane+1

    float adh = __ldg(&g_ad1[d * HEADS + hc]);
    // self-loop (ew = 1)
    float e0 = __expf(leaky(__ldg(&g_as1[d * HEADS + hc]) + adh));
    float den = e0;
    float2 hv = *(const float2*)(g_h1 + (size_t)d * H1C + lane * 2);
    float2 acc = make_float2(e0 * hv.x, e0 * hv.y);

    int beg = g_off[d], end = g_cur[d];
    for (int base = beg; base < end; base += 32) {
        int idx = base + lane;
        int2 sw = make_int2(0, 0);
        if (idx < end) sw = __ldg(&g_sw[idx]);
        int m = min(32, end - base);
        int m8 = (m + 7) & ~7;
        for (int j = 0; j < m8; j += 8) {
#pragma unroll
            for (int jj = 0; jj < 8; jj++) {
                int jc = j + jj;
                int s = __shfl_sync(0xffffffffu, sw.x, jc);
                float wj = __int_as_float(__shfl_sync(0xffffffffu, sw.y, jc));
                float e = __expf(leaky(__ldg(&g_as1[s * HEADS + hc]) + adh));
                if (jc < m) den += e;
                float w = e * wj;   // wj = 0 for pad
                float2 sv = *(const float2*)(g_h1 + (size_t)s * H1C + lane * 2);
                acc.x += w * sv.x;
                acc.y += w * sv.y;
            }
        }
    }
    float inv = 1.f / (den + 1e-16f);
    float2 bb = *(const float2*)(b1 + lane * 2);
    float zx = acc.x * inv + bb.x;
    float zy = acc.y * inv + bb.y;
    zx = zx > 0.f ? zx : __expf(zx) - 1.f;
    zy = zy > 0.f ? zy : __expf(zy) - 1.f;
    *(float2*)(g_z + (size_t)d * H1C + lane * 2) = make_float2(zx, zy);
}

// ================= K_gemm2: z@W2 + attention ==================================
// block 256 = 128 nodes x 8 col-groups (5 cols); thread = 4 nodes x 5 cols
__global__ __launch_bounds__(256) void k_gemm2(
    const float* __restrict__ W2, const float* __restrict__ att_s,
    const float* __restrict__ att_d)
{
    __shared__ float sz[128 * 68];
    __shared__ float sw4[64 * 32];
    __shared__ float sw1[64 * 8];
    int tid = threadIdx.x;
    int node0 = blockIdx.x * 128;

    const float4* z4 = (const float4*)g_z;
#pragma unroll
    for (int i = 0; i < 8; i++) {
        int idx = tid + i * 256;
        int r = idx >> 4, c = idx & 15;
        int n = node0 + r;
        float4 v = make_float4(0.f, 0.f, 0.f, 0.f);
        if (n < NN) v = z4[(size_t)n * 16 + c];
        *(float4*)(sz + r * 68 + c * 4) = v;
    }
#pragma unroll
    for (int i = 0; i < 10; i++) {
        int idx = tid + i * 256;
        int k = idx / OUTC, r = idx - k * OUTC;
        int cgg = r / 5, j = r - cgg * 5;
        float v = W2[idx];
        if (j < 4) sw4[k * 32 + cgg * 4 + j] = v;
        else       sw1[k * 8 + cgg] = v;
    }
    __syncthreads();

    int cg = tid & 7;
    int ng = tid >> 3;
    int c0 = cg * 5;
    const float* zr0 = sz + (ng * 4 + 0) * 68;
    const float* zr1 = sz + (ng * 4 + 1) * 68;
    const float* zr2 = sz + (ng * 4 + 2) * 68;
    const float* zr3 = sz + (ng * 4 + 3) * 68;

    float acc[4][5];
#pragma unroll
    for (int i = 0; i < 4; i++)
#pragma unroll
        for (int c = 0; c < 5; c++) acc[i][c] = 0.f;

#pragma unroll 4
    for (int k = 0; k < H1C; k++) {
        float4 w = *(const float4*)(sw4 + k * 32 + cg * 4);
        float w5 = sw1[k * 8 + cg];
        float z0 = zr0[k], z1 = zr1[k], z2 = zr2[k], z3 = zr3[k];
        acc[0][0] += z0 * w.x; acc[0][1] += z0 * w.y; acc[0][2] += z0 * w.z; acc[0][3] += z0 * w.w; acc[0][4] += z0 * w5;
        acc[1][0] += z1 * w.x; acc[1][1] += z1 * w.y; acc[1][2] += z1 * w.z; acc[1][3] += z1 * w.w; acc[1][4] += z1 * w5;
        acc[2][0] += z2 * w.x; acc[2][1] += z2 * w.y; acc[2][2] += z2 * w.z; acc[2][3] += z2 * w.w; acc[2][4] += z2 * w5;
        acc[3][0] += z3 * w.x; acc[3][1] += z3 * w.y; acc[3][2] += z3 * w.z; acc[3][3] += z3 * w.w; acc[3][4] += z3 * w5;
    }

    float ats[5], atd[5];
#pragma unroll
    for (int c = 0; c < 5; c++) { ats[c] = __ldg(&att_s[c0 + c]); atd[c] = __ldg(&att_d[c0 + c]); }

#pragma unroll
    for (int i = 0; i < 4; i++) {
        float s_ = 0.f, d_ = 0.f;
#pragma unroll
        for (int c = 0; c < 5; c++) { s_ += acc[i][c] * ats[c]; d_ += acc[i][c] * atd[c]; }
        s_ += __shfl_xor_sync(0xffffffffu, s_, 1);
        d_ += __shfl_xor_sync(0xffffffffu, d_, 1);
        s_ += __shfl_xor_sync(0xffffffffu, s_, 2);
        d_ += __shfl_xor_sync(0xffffffffu, d_, 2);
        s_ += __shfl_xor_sync(0xffffffffu, s_, 4);
        d_ += __shfl_xor_sync(0xffffffffu, d_, 4);
        int nd = node0 + ng * 4 + i;
        if (nd < NN) {
            if (cg == 0) {
                g_as2[nd] = s_;
                g_ad2[nd] = d_;
            }
            float* hp = g_h2 + (size_t)nd * OUTC + c0;
#pragma unroll
            for (int c = 0; c < 5; c++) hp[c] = acc[i][c];
        }
    }
}

// ================= K_agg2: warp-per-node gather (layer 2) + output ===========
__global__ __launch_bounds__(256) void k_agg2(
    float* __restrict__ out, const float* __restrict__ b2, int n)
{
    int d = blockIdx.x * 8 + (threadIdx.x >> 5);
    if (d >= n) return;
    int lane = threadIdx.x & 31;

    float add = __ldg(&g_ad2[d]);
    float e0 = __expf(leaky(__ldg(&g_as2[d]) + add));   // self loop
    float den = e0;
    float2 acc = make_float2(0.f, 0.f);
    if (lane < 20) {
        float2 hv = *(const float2*)(g_h2 + (size_t)d * OUTC + lane * 2);
        acc.x = e0 * hv.x;
        acc.y = e0 * hv.y;
    }

    int beg = g_off[d], end = g_cur[d];
    for (int base = beg; base < end; base += 32) {
        int idx = base + lane;
        int2 sw = make_int2(0, 0);
        if (idx < end) sw = __ldg(&g_sw[idx]);
        int m = min(32, end - base);
        int m8 = (m + 7) & ~7;
        for (int j = 0; j < m8; j += 8) {
#pragma unroll
            for (int jj = 0; jj < 8; jj++) {
                int jc = j + jj;
                int s = __shfl_sync(0xffffffffu, sw.x, jc);
                float wj = __int_as_float(__shfl_sync(0xffffffffu, sw.y, jc));
                float e = __expf(leaky(__ldg(&g_as2[s]) + add));
                if (jc < m) den += e;
                float w = e * wj;
                if (lane < 20) {
                    float2 sv = *(const float2*)(g_h2 + (size_t)s * OUTC + lane * 2);
                    acc.x += w * sv.x;
                    acc.y += w * sv.y;
                }
            }
        }
    }
    float inv = 1.f / (den + 1e-16f);
    if (lane < 20) {
        float2 bb = *(const float2*)(b2 + lane * 2);
        float2 r = make_float2(acc.x * inv + bb.x, acc.y * inv + bb.y);
        *(float2*)(out + (size_t)d * OUTC + lane * 2) = r;
    }
}

// -----------------------------------------------------------------------------
extern "C" void kernel_launch(void* const* d_in, const int* in_sizes, int n_in,
                              void* d_out, int out_size)
{
    const float* x   = (const float*)d_in[0];
    const int*   ei  = (const int*)d_in[1];
    const float* ew  = (const float*)d_in[2];
    const float* W1  = (const float*)d_in[3];
    const float* as1 = (const float*)d_in[4];
    const float* ad1 = (const float*)d_in[5];
    const float* b1  = (const float*)d_in[6];
    const float* W2  = (const float*)d_in[7];
    const float* as2 = (const float*)d_in[8];
    const float* ad2 = (const float*)d_in[9];
    const float* b2  = (const float*)d_in[10];

    int n = in_sizes[0] / INC;       // 100000
    int e = in_sizes[2];             // 1600000

    // gemm1 first: produces h1/as1/ad1 AND re-zeros g_cnt/g_total
    k_gemm1<<<(n + 127) / 128, 256>>>(x, W1, as1, ad1);
    // CSR build
    k_hist<<<(e + 255) / 256, 256>>>(ei, e);
    k_off<<<(n + 255) / 256, 256>>>(n);
    k_scatter<<<(e + 255) / 256, 256>>>(ei, ew, e);
    // layer 1 aggregation
    k_agg1<<<(n + 7) / 8, 256>>>(b1, n);
    // layer 2
    k_gemm2<<<(n + 127) / 128, 256>>>(W2, as2, ad2);
    k_agg2<<<(n + 7) / 8, 256>>>((float*)d_out, b2, n);
}